// round 11
// baseline (speedup 1.0000x reference)
#include <cuda_runtime.h>
#include <cuda_bf16.h>
#include <stdint.h>
#include <math.h>

#define TOKENS 4096
#define DIM    2048
#define NEXP   32
#define TOPK   8
#define MDIM   768
#define NROWS  (TOKENS*TOPK)
#define BM     128
#define MAX_TILES 288

__device__ __forceinline__ uint32_t smem_u32(const void* p) {
    uint32_t a;
    asm("{ .reg .u64 t; cvta.to.shared.u64 t, %1; cvt.u32.u64 %0, t; }" : "=r"(a) : "l"(p));
    return a;
}
__device__ __forceinline__ void cpasync16(uint32_t s, const void* g) {
    asm volatile("cp.async.cg.shared.global [%0], [%1], 16;" :: "r"(s), "l"(g) : "memory");
}
#define CP_COMMIT() asm volatile("cp.async.commit_group;" ::: "memory")
#define CP_WAIT0()  asm volatile("cp.async.wait_group 0;" ::: "memory")

#define LDSM4(r, addr) \
    asm volatile("ldmatrix.sync.aligned.m8n8.x4.shared.b16 {%0,%1,%2,%3}, [%4];" \
        : "=r"((r)[0]), "=r"((r)[1]), "=r"((r)[2]), "=r"((r)[3]) : "r"(addr))

#define LDSM4T(r, addr) \
    asm volatile("ldmatrix.sync.aligned.m8n8.x4.trans.shared.b16 {%0,%1,%2,%3}, [%4];" \
        : "=r"((r)[0]), "=r"((r)[1]), "=r"((r)[2]), "=r"((r)[3]) : "r"(addr))

#define MMA_BF16(d, a, b0v, b1v) \
    asm volatile("mma.sync.aligned.m16n8k16.row.col.f32.bf16.bf16.f32 " \
        "{%0,%1,%2,%3},{%4,%5,%6,%7},{%8,%9},{%0,%1,%2,%3};" \
        : "+f"((d)[0]), "+f"((d)[1]), "+f"((d)[2]), "+f"((d)[3]) \
        : "r"((a)[0]), "r"((a)[1]), "r"((a)[2]), "r"((a)[3]), "r"(b0v), "r"(b1v))

// 4 MMAs: two A row-halves x two n8-groups from one LDSM4T
#define MMA4(acc, j0, A0, A1, b) do { \
    MMA_BF16(acc[0][j0],   A0, (b)[0], (b)[1]); \
    MMA_BF16(acc[0][j0+1], A0, (b)[2], (b)[3]); \
    MMA_BF16(acc[1][j0],   A1, (b)[0], (b)[1]); \
    MMA_BF16(acc[1][j0+1], A1, (b)[2], (b)[3]); \
} while(0)

__device__ __forceinline__ void split2(float v, __nv_bfloat16& h, __nv_bfloat16& l) {
    h = __float2bfloat16(v);
    l = __float2bfloat16(v - __bfloat162float(h));
}
__device__ __forceinline__ uint32_t pack2(__nv_bfloat16 a, __nv_bfloat16 b) {
    __nv_bfloat162 t(a, b);
    return *(uint32_t*)&t;
}
__device__ __forceinline__ void split4pack(float4 v, uint2& hh, uint2& ll) {
    __nv_bfloat16 h0, h1, h2, h3, l0, l1, l2, l3;
    split2(v.x, h0, l0); split2(v.y, h1, l1);
    split2(v.z, h2, l2); split2(v.w, h3, l3);
    hh = make_uint2(pack2(h0, h1), pack2(h2, h3));
    ll = make_uint2(pack2(l0, l1), pack2(l2, l3));
}

// ============ device scratch (~402MB, proven budget) ============
__device__ int   g_off[NEXP + 1];
__device__ int   g_expert_of[NROWS];
__device__ float g_weight_of[NROWS];
__device__ int   g_row_token[NROWS];
__device__ int   g_pos_of[NROWS];
__device__ int   g_tile_expert[MAX_TILES];
__device__ int   g_tile_row[MAX_TILES];
__device__ int   g_num_tiles;
__device__ __nv_bfloat16 g_Xh[(size_t)TOKENS * DIM];
__device__ __nv_bfloat16 g_Xl[(size_t)TOKENS * DIM];
__device__ __nv_bfloat16 g_Ih[(size_t)NROWS * MDIM];
__device__ __nv_bfloat16 g_Il[(size_t)NROWS * MDIM];
__device__ float g_eout[(size_t)NROWS * DIM];

// ============ token fp32 -> split bf16 (launch #1) ============
__global__ __launch_bounds__(256) void k_convert_x(const float* __restrict__ x) {
    int t = blockIdx.x;
    const float4* src = (const float4*)(x + (size_t)t * DIM);
#pragma unroll
    for (int i = 0; i < 2; i++) {
        int idx = threadIdx.x + i * 256;
        uint2 hh, ll;
        split4pack(src[idx], hh, ll);
        *(uint2*)(g_Xh + (size_t)t * DIM + idx * 4) = hh;
        *(uint2*)(g_Xl + (size_t)t * DIM + idx * 4) = ll;
    }
}

// ============ router (launch #2) ============
__global__ __launch_bounds__(256) void k_router(const float* __restrict__ x,
                                                const float* __restrict__ gk) {
    __shared__ float xs[64][64];
    __shared__ float gs[64][32];
    __shared__ float lg[64][32];
    int tid = threadIdx.x, t0 = blockIdx.x * 64, e = tid & 31, r8 = tid >> 5;
    float acc[8];
#pragma unroll
    for (int i = 0; i < 8; i++) acc[i] = 0.f;
    for (int d0 = 0; d0 < DIM; d0 += 64) {
#pragma unroll
        for (int i = 0; i < 4; i++) {
            int f = tid + i * 256, row = f >> 4, dv = f & 15;
            *(float4*)&xs[row][dv * 4] =
                *(const float4*)(x + (size_t)(t0 + row) * DIM + d0 + dv * 4);
        }
#pragma unroll
        for (int i = 0; i < 2; i++) {
            int f = tid + i * 256, dd = f >> 3, ev = f & 7;
            *(float4*)&gs[dd][ev * 4] =
                *(const float4*)(gk + (size_t)(d0 + dd) * NEXP + ev * 4);
        }
        __syncthreads();
#pragma unroll 8
        for (int dd = 0; dd < 64; dd++) {
            float g = gs[dd][e];
#pragma unroll
            for (int rr = 0; rr < 8; rr++) acc[rr] += xs[rr * 8 + r8][dd] * g;
        }
        __syncthreads();
    }
#pragma unroll
    for (int rr = 0; rr < 8; rr++) lg[rr * 8 + r8][e] = acc[rr];
    __syncthreads();

    int w = tid >> 5, lane = tid & 31;
    for (int ti = 0; ti < 8; ti++) {
        int tok = w * 8 + ti;
        float logit = lg[tok][lane];
        unsigned selmask = 0;
        float vals[TOPK]; int ids[TOPK];
#pragma unroll
        for (int k = 0; k < TOPK; k++) {
            float v = ((selmask >> lane) & 1u) ? -1e30f : logit;
            float bv = v; int bi = lane;
#pragma unroll
            for (int off = 16; off; off >>= 1) {
                float ov = __shfl_down_sync(0xffffffffu, bv, off);
                int   oi = __shfl_down_sync(0xffffffffu, bi, off);
                if (ov > bv || (ov == bv && oi < bi)) { bv = ov; bi = oi; }
            }
            bv = __shfl_sync(0xffffffffu, bv, 0);
            bi = __shfl_sync(0xffffffffu, bi, 0);
            vals[k] = bv; ids[k] = bi;
            selmask |= 1u << bi;
        }
        if (lane == 0) {
            float mx = vals[0], s = 0.f, wv[TOPK];
#pragma unroll
            for (int k = 0; k < TOPK; k++) { wv[k] = expf(vals[k] - mx); s += wv[k]; }
            float inv = 1.f / s;
            int t = t0 + tok;
#pragma unroll
            for (int k = 0; k < TOPK; k++) {
                g_weight_of[t * TOPK + k] = wv[k] * inv;
                g_expert_of[t * TOPK + k] = ids[k];
            }
        }
    }
}

// ============ fused histogram + prefix + tile map + scatter (launch #3) ============
__global__ __launch_bounds__(1024) void k_prefix_scatter() {
    __shared__ int cnt[NEXP], off_s[NEXP + 1], cur[NEXP];
    int tid = threadIdx.x;
    if (tid < NEXP) { cnt[tid] = 0; cur[tid] = 0; }
    __syncthreads();
    for (int i = tid; i < NROWS; i += 1024)
        atomicAdd(&cnt[g_expert_of[i]], 1);
    __syncthreads();
    if (tid < 32) {
        int c = (tid < NEXP) ? cnt[tid] : 0;
        int s = c;
#pragma unroll
        for (int off = 1; off < 32; off <<= 1) {
            int v = __shfl_up_sync(0xffffffffu, s, off);
            if (tid >= off) s += v;
        }
        if (tid < NEXP) off_s[tid + 1] = s;
        if (tid == 0) off_s[0] = 0;
    }
    __syncthreads();
    if (tid <= NEXP) g_off[tid] = off_s[tid];
    if (tid == 0) {
        int nt = 0;
        for (int e = 0; e < NEXP; e++) {
            int cc = cnt[e], base = off_s[e];
            for (int r = 0; r < cc; r += BM) {
                g_tile_expert[nt] = e;
                g_tile_row[nt] = base + r;
                nt++;
            }
        }
        g_num_tiles = nt;
    }
    for (int i = tid; i < NROWS; i += 1024) {
        int e = g_expert_of[i];
        int p = off_s[e] + atomicAdd(&cur[e], 1);
        g_row_token[p] = i >> 3;
        g_pos_of[i] = p;
    }
}

// ============ GEMM1 (launch #4): gate+up, 128Mx128N, 512 threads (16 warps) ============
// smem: A 2 stages x (Ah 6144 + Al 6144) @0..24576 (48B rows)
//       B k-major (16 x 272B): gh@24576 gl@28928 uh@33280 ul@37632 ; total 41984
__global__ __launch_bounds__(512) void k_gemm1(const float* __restrict__ Wg,
                                               const float* __restrict__ Wu) {
    int mt = blockIdx.y;
    if (mt >= g_num_tiles) return;
    int e = g_tile_expert[mt], row0 = g_tile_row[mt], row_end = g_off[e + 1];
    int n0 = blockIdx.x * 128;

    __shared__ __align__(128) char smem[41984];
    uint32_t sb = smem_u32(smem);
    int tid = threadIdx.x, wid = tid >> 5, lane = tid & 31;
    int wm0 = (wid & 3) * 32, wn0 = (wid >> 2) * 32;

    // A fill: 512 chunks/stage, 1/thread
    const __nv_bfloat16* gA; uint32_t soA;
    {
        int c = tid;
        int half = c >> 8, rem = c & 255, row = rem >> 1, q = rem & 1;
        int gr = row0 + row; if (gr > NROWS - 1) gr = NROWS - 1;
        int tok = g_row_token[gr];
        gA = (half ? g_Xl : g_Xh) + (size_t)tok * DIM + q * 8;
        soA = half * 6144 + row * 48 + q * 16;
    }
    // W fill: 1024 float4/chunk, 2/thread
    const float* gW[2]; int wkr[2], wnq[2], wmat[2];
#pragma unroll
    for (int i = 0; i < 2; i++) {
        int c = tid + i * 512;
        int mat = c >> 9, rem = c & 511, kr = rem >> 5, nq = rem & 31;
        const float* W = mat ? Wu : Wg;
        gW[i] = W + ((size_t)e * DIM + kr) * MDIM + n0 + nq * 4;
        wkr[i] = kr; wnq[i] = nq; wmat[i] = mat;
    }

    float accG[2][4][4] = {}, accU[2][4][4] = {};
    uint32_t aOff = (wm0 + (lane & 15)) * 48 + (lane >> 4) * 16;
    uint32_t bT = ((lane & 7) + ((lane >> 3) & 1) * 8) * 272
                + ((lane >> 4) & 1) * 16 + wn0 * 2;

    float4 wreg[2];
    cpasync16(sb + soA, gA);
#pragma unroll
    for (int i = 0; i < 2; i++) wreg[i] = *(const float4*)(gW[i]);
    CP_COMMIT();

    const int NCH = DIM / 16;  // 128
    for (int kc = 0; kc < NCH; kc++) {
        int st = kc & 1;
        CP_WAIT0();
        __syncthreads();   // A(kc) ready; B(kc-1) reads retired
        if (kc + 1 < NCH) {
            cpasync16(sb + (st ^ 1) * 12288 + soA, gA + (kc + 1) * 16);
            CP_COMMIT();
        }
#pragma unroll
        for (int i = 0; i < 2; i++) {
            uint2 hh, ll;
            split4pack(wreg[i], hh, ll);
            char* base = smem + 24576 + wmat[i] * 8704 + wkr[i] * 272 + wnq[i] * 8;
            *(uint2*)base = hh;
            *(uint2*)(base + 4352) = ll;
        }
        if (kc + 1 < NCH) {
#pragma unroll
            for (int i = 0; i < 2; i++)
                wreg[i] = *(const float4*)(gW[i] + (size_t)(kc + 1) * 16 * MDIM);
        }
        __syncthreads();   // B published
        uint32_t aA = sb + st * 12288 + aOff;
        uint32_t aH0[4], aH1[4], aL0[4], aL1[4];
        LDSM4(aH0, aA); LDSM4(aH1, aA + 768);
        LDSM4(aL0, aA + 6144); LDSM4(aL1, aA + 6912);
        uint32_t bb = sb + 24576 + bT;
#pragma unroll
        for (int g = 0; g < 2; g++) {
            uint32_t b[4];
            int j0 = 2 * g;
            LDSM4T(b, bb + g * 32);            // gate hi
            MMA4(accG, j0, aH0, aH1, b);
            MMA4(accG, j0, aL0, aL1, b);
            LDSM4T(b, bb + 4352 + g * 32);     // gate lo (Ah only)
            MMA4(accG, j0, aH0, aH1, b);
            LDSM4T(b, bb + 8704 + g * 32);     // up hi
            MMA4(accU, j0, aH0, aH1, b);
            MMA4(accU, j0, aL0, aL1, b);
            LDSM4T(b, bb + 13056 + g * 32);    // up lo (Ah only)
            MMA4(accU, j0, aH0, aH1, b);
        }
    }

    // epilogue: silu(g)*u -> split bf16
#pragma unroll
    for (int f = 0; f < 2; f++) {
        int rl = row0 + wm0 + f * 16 + (lane >> 2);
        int rh = rl + 8;
#pragma unroll
        for (int j = 0; j < 4; j++) {
            int c = n0 + wn0 + j * 8 + (lane & 3) * 2;
            float g0 = accG[f][j][0], g1 = accG[f][j][1];
            float g2 = accG[f][j][2], g3 = accG[f][j][3];
            float u0 = accU[f][j][0], u1 = accU[f][j][1];
            float u2 = accU[f][j][2], u3 = accU[f][j][3];
            float v0 = (g0 / (1.f + __expf(-g0))) * u0;
            float v1 = (g1 / (1.f + __expf(-g1))) * u1;
            float v2 = (g2 / (1.f + __expf(-g2))) * u2;
            float v3 = (g3 / (1.f + __expf(-g3))) * u3;
            __nv_bfloat16 h0, l0, h1, l1, h2, l2, h3, l3;
            split2(v0, h0, l0); split2(v1, h1, l1);
            split2(v2, h2, l2); split2(v3, h3, l3);
            if (rl < row_end) {
                *(uint32_t*)(g_Ih + (size_t)rl * MDIM + c) = pack2(h0, h1);
                *(uint32_t*)(g_Il + (size_t)rl * MDIM + c) = pack2(l0, l1);
            }
            if (rh < row_end) {
                *(uint32_t*)(g_Ih + (size_t)rh * MDIM + c) = pack2(h2, h3);
                *(uint32_t*)(g_Il + (size_t)rh * MDIM + c) = pack2(l2, l3);
            }
        }
    }
}

// ============ GEMM2 (launch #5): down proj, 128Mx128N, 512 threads ============
// smem: A 2 x (h 6144 + l 6144) @0..24576; B: h@24576 l@28928; total 33280
__global__ __launch_bounds__(512) void k_gemm2(const float* __restrict__ Wd) {
    int mt = blockIdx.y;
    if (mt >= g_num_tiles) return;
    int e = g_tile_expert[mt], row0 = g_tile_row[mt], row_end = g_off[e + 1];
    int n0 = blockIdx.x * 128;

    __shared__ __align__(128) char smem[33280];
    uint32_t sb = smem_u32(smem);
    int tid = threadIdx.x, wid = tid >> 5, lane = tid & 31;
    int wm0 = (wid & 3) * 32, wn0 = (wid >> 2) * 32;

    const __nv_bfloat16* gA; uint32_t soA;
    {
        int c = tid;
        int half = c >> 8, rem = c & 255, row = rem >> 1, q = rem & 1;
        int gr = row0 + row; if (gr > NROWS - 1) gr = NROWS - 1;
        gA = (half ? g_Il : g_Ih) + (size_t)gr * MDIM + q * 8;
        soA = half * 6144 + row * 48 + q * 16;
    }
    int wkr = tid >> 5, wnq = tid & 31;
    const float* gW = Wd + ((size_t)e * MDIM + wkr) * DIM + n0 + wnq * 4;

    float acc[2][4][4] = {};
    uint32_t aOff = (wm0 + (lane & 15)) * 48 + (lane >> 4) * 16;
    uint32_t bT = ((lane & 7) + ((lane >> 3) & 1) * 8) * 272
                + ((lane >> 4) & 1) * 16 + wn0 * 2;

    float4 wreg;
    cpasync16(sb + soA, gA);
    wreg = *(const float4*)(gW);
    CP_COMMIT();

    const int NCH = MDIM / 16;  // 48
    for (int kc = 0; kc < NCH; kc++) {
        int st = kc & 1;
        CP_WAIT0();
        __syncthreads();
        if (kc + 1 < NCH) {
            cpasync16(sb + (st ^ 1) * 12288 + soA, gA + (kc + 1) * 16);
            CP_COMMIT();
        }
        {
            uint2 hh, ll;
            split4pack(wreg, hh, ll);
            char* base = smem + 24576 + wkr * 272 + wnq * 8;
            *(uint2*)base = hh;
            *(uint2*)(base + 4352) = ll;
        }
        if (kc + 1 < NCH)
            wreg = *(const float4*)(gW + (size_t)(kc + 1) * 16 * DIM);
        __syncthreads();
        uint32_t aA = sb + st * 12288 + aOff;
        uint32_t aH0[4], aH1[4], aL0[4], aL1[4];
        LDSM4(aH0, aA); LDSM4(aH1, aA + 768);
        LDSM4(aL0, aA + 6144); LDSM4(aL1, aA + 6912);
        uint32_t bb = sb + 24576 + bT;
#pragma unroll
        for (int g = 0; g < 2; g++) {
            uint32_t b[4];
            int j0 = 2 * g;
            LDSM4T(b, bb + g * 32);            // down hi
            MMA4(acc, j0, aH0, aH1, b);
            MMA4(acc, j0, aL0, aL1, b);
            LDSM4T(b, bb + 4352 + g * 32);     // down lo (Ah only)
            MMA4(acc, j0, aH0, aH1, b);
        }
    }

#pragma unroll
    for (int f = 0; f < 2; f++) {
        int rl = row0 + wm0 + f * 16 + (lane >> 2);
        int rh = rl + 8;
#pragma unroll
        for (int j = 0; j < 4; j++) {
            int c = n0 + wn0 + j * 8 + (lane & 3) * 2;
            if (rl < row_end)
                *(float2*)(g_eout + (size_t)rl * DIM + c) = make_float2(acc[f][j][0], acc[f][j][1]);
            if (rh < row_end)
                *(float2*)(g_eout + (size_t)rh * DIM + c) = make_float2(acc[f][j][2], acc[f][j][3]);
        }
    }
}

// ============ combine (launch #6) ============
__global__ __launch_bounds__(256) void k_combine(float* __restrict__ out) {
    int t = blockIdx.x;
    __shared__ float w[TOPK];
    __shared__ int   ps[TOPK];
    if (threadIdx.x < TOPK) {
        w[threadIdx.x]  = g_weight_of[t * TOPK + threadIdx.x];
        ps[threadIdx.x] = g_pos_of[t * TOPK + threadIdx.x];
    }
    __syncthreads();
    for (int d = threadIdx.x; d < DIM; d += 256) {
        float s = 0.f;
#pragma unroll
        for (int k = 0; k < TOPK; k++)
            s += w[k] * g_eout[(size_t)ps[k] * DIM + d];
        out[(size_t)t * DIM + d] = s;
    }
}

// ============ launch ============
extern "C" void kernel_launch(void* const* d_in, const int* in_sizes, int n_in,
                              void* d_out, int out_size) {
    const float* x  = (const float*)d_in[0];
    const float* gk = (const float*)d_in[1];
    const float* wg = (const float*)d_in[2];
    const float* wu = (const float*)d_in[3];
    const float* wd = (const float*)d_in[4];
    float* out = (float*)d_out;

    k_convert_x<<<TOKENS, 256>>>(x);
    k_router<<<TOKENS / 64, 256>>>(x, gk);
    k_prefix_scatter<<<1, 1024>>>();
    k_gemm1<<<dim3(MDIM / 128, MAX_TILES), 512>>>(wg, wu);
    k_gemm2<<<dim3(DIM / 128, MAX_TILES), 512>>>(wd);
    k_combine<<<TOKENS, 256>>>(out);
}

// round 12
// speedup vs baseline: 1.1725x; 1.1725x over previous
#include <cuda_runtime.h>
#include <cuda_bf16.h>
#include <stdint.h>
#include <math.h>

#define TOKENS 4096
#define DIM    2048
#define NEXP   32
#define TOPK   8
#define MDIM   768
#define NROWS  (TOKENS*TOPK)
#define BM     128
#define MAX_TILES 288

__device__ __forceinline__ uint32_t smem_u32(const void* p) {
    uint32_t a;
    asm("{ .reg .u64 t; cvta.to.shared.u64 t, %1; cvt.u32.u64 %0, t; }" : "=r"(a) : "l"(p));
    return a;
}

#define LDSM4(r, addr) \
    asm volatile("ldmatrix.sync.aligned.m8n8.x4.shared.b16 {%0,%1,%2,%3}, [%4];" \
        : "=r"((r)[0]), "=r"((r)[1]), "=r"((r)[2]), "=r"((r)[3]) : "r"(addr))

#define LDSM4T(r, addr) \
    asm volatile("ldmatrix.sync.aligned.m8n8.x4.trans.shared.b16 {%0,%1,%2,%3}, [%4];" \
        : "=r"((r)[0]), "=r"((r)[1]), "=r"((r)[2]), "=r"((r)[3]) : "r"(addr))

#define MMA_BF16(d, a, b0v, b1v) \
    asm volatile("mma.sync.aligned.m16n8k16.row.col.f32.bf16.bf16.f32 " \
        "{%0,%1,%2,%3},{%4,%5,%6,%7},{%8,%9},{%0,%1,%2,%3};" \
        : "+f"((d)[0]), "+f"((d)[1]), "+f"((d)[2]), "+f"((d)[3]) \
        : "r"((a)[0]), "r"((a)[1]), "r"((a)[2]), "r"((a)[3]), "r"(b0v), "r"(b1v))

#define MMA4(acc, j0, A0, A1, b) do { \
    MMA_BF16(acc[0][j0],   A0, (b)[0], (b)[1]); \
    MMA_BF16(acc[0][j0+1], A0, (b)[2], (b)[3]); \
    MMA_BF16(acc[1][j0],   A1, (b)[0], (b)[1]); \
    MMA_BF16(acc[1][j0+1], A1, (b)[2], (b)[3]); \
} while(0)

__device__ __forceinline__ void split2(float v, __nv_bfloat16& h, __nv_bfloat16& l) {
    h = __float2bfloat16(v);
    l = __float2bfloat16(v - __bfloat162float(h));
}
__device__ __forceinline__ uint32_t pack2(__nv_bfloat16 a, __nv_bfloat16 b) {
    __nv_bfloat162 t(a, b);
    return *(uint32_t*)&t;
}
__device__ __forceinline__ void split4pack(float4 v, uint2& hh, uint2& ll) {
    __nv_bfloat16 h0, h1, h2, h3, l0, l1, l2, l3;
    split2(v.x, h0, l0); split2(v.y, h1, l1);
    split2(v.z, h2, l2); split2(v.w, h3, l3);
    hh = make_uint2(pack2(h0, h1), pack2(h2, h3));
    ll = make_uint2(pack2(l0, l1), pack2(l2, l3));
}

// ============ device scratch (~402MB, proven budget) ============
__device__ int   g_off[NEXP + 1];
__device__ int   g_expert_of[NROWS];
__device__ float g_weight_of[NROWS];
__device__ int   g_row_token[NROWS];
__device__ int   g_pos_of[NROWS];
__device__ int   g_tile_expert[MAX_TILES];
__device__ int   g_tile_row[MAX_TILES];
__device__ int   g_num_tiles;
__device__ __nv_bfloat16 g_Xh[(size_t)TOKENS * DIM];
__device__ __nv_bfloat16 g_Xl[(size_t)TOKENS * DIM];
__device__ __nv_bfloat16 g_Ih[(size_t)NROWS * MDIM];
__device__ __nv_bfloat16 g_Il[(size_t)NROWS * MDIM];
__device__ float g_eout[(size_t)NROWS * DIM];

// ============ token fp32 -> split bf16 (launch #1) ============
__global__ __launch_bounds__(256) void k_convert_x(const float* __restrict__ x) {
    int t = blockIdx.x;
    const float4* src = (const float4*)(x + (size_t)t * DIM);
#pragma unroll
    for (int i = 0; i < 2; i++) {
        int idx = threadIdx.x + i * 256;
        uint2 hh, ll;
        split4pack(src[idx], hh, ll);
        *(uint2*)(g_Xh + (size_t)t * DIM + idx * 4) = hh;
        *(uint2*)(g_Xl + (size_t)t * DIM + idx * 4) = ll;
    }
}

// ============ router (launch #2) ============
__global__ __launch_bounds__(256) void k_router(const float* __restrict__ x,
                                                const float* __restrict__ gk) {
    __shared__ float xs[64][64];
    __shared__ float gs[64][32];
    __shared__ float lg[64][32];
    int tid = threadIdx.x, t0 = blockIdx.x * 64, e = tid & 31, r8 = tid >> 5;
    float acc[8];
#pragma unroll
    for (int i = 0; i < 8; i++) acc[i] = 0.f;
    for (int d0 = 0; d0 < DIM; d0 += 64) {
#pragma unroll
        for (int i = 0; i < 4; i++) {
            int f = tid + i * 256, row = f >> 4, dv = f & 15;
            *(float4*)&xs[row][dv * 4] =
                *(const float4*)(x + (size_t)(t0 + row) * DIM + d0 + dv * 4);
        }
#pragma unroll
        for (int i = 0; i < 2; i++) {
            int f = tid + i * 256, dd = f >> 3, ev = f & 7;
            *(float4*)&gs[dd][ev * 4] =
                *(const float4*)(gk + (size_t)(d0 + dd) * NEXP + ev * 4);
        }
        __syncthreads();
#pragma unroll 8
        for (int dd = 0; dd < 64; dd++) {
            float g = gs[dd][e];
#pragma unroll
            for (int rr = 0; rr < 8; rr++) acc[rr] += xs[rr * 8 + r8][dd] * g;
        }
        __syncthreads();
    }
#pragma unroll
    for (int rr = 0; rr < 8; rr++) lg[rr * 8 + r8][e] = acc[rr];
    __syncthreads();

    int w = tid >> 5, lane = tid & 31;
    for (int ti = 0; ti < 8; ti++) {
        int tok = w * 8 + ti;
        float logit = lg[tok][lane];
        unsigned selmask = 0;
        float vals[TOPK]; int ids[TOPK];
#pragma unroll
        for (int k = 0; k < TOPK; k++) {
            float v = ((selmask >> lane) & 1u) ? -1e30f : logit;
            float bv = v; int bi = lane;
#pragma unroll
            for (int off = 16; off; off >>= 1) {
                float ov = __shfl_down_sync(0xffffffffu, bv, off);
                int   oi = __shfl_down_sync(0xffffffffu, bi, off);
                if (ov > bv || (ov == bv && oi < bi)) { bv = ov; bi = oi; }
            }
            bv = __shfl_sync(0xffffffffu, bv, 0);
            bi = __shfl_sync(0xffffffffu, bi, 0);
            vals[k] = bv; ids[k] = bi;
            selmask |= 1u << bi;
        }
        if (lane == 0) {
            float mx = vals[0], s = 0.f, wv[TOPK];
#pragma unroll
            for (int k = 0; k < TOPK; k++) { wv[k] = expf(vals[k] - mx); s += wv[k]; }
            float inv = 1.f / s;
            int t = t0 + tok;
#pragma unroll
            for (int k = 0; k < TOPK; k++) {
                g_weight_of[t * TOPK + k] = wv[k] * inv;
                g_expert_of[t * TOPK + k] = ids[k];
            }
        }
    }
}

// ============ fused histogram + prefix + tile map + scatter (launch #3) ============
__global__ __launch_bounds__(1024) void k_prefix_scatter() {
    __shared__ int cnt[NEXP], off_s[NEXP + 1], cur[NEXP];
    int tid = threadIdx.x;
    if (tid < NEXP) { cnt[tid] = 0; cur[tid] = 0; }
    __syncthreads();
    for (int i = tid; i < NROWS; i += 1024)
        atomicAdd(&cnt[g_expert_of[i]], 1);
    __syncthreads();
    if (tid < 32) {
        int c = (tid < NEXP) ? cnt[tid] : 0;
        int s = c;
#pragma unroll
        for (int off = 1; off < 32; off <<= 1) {
            int v = __shfl_up_sync(0xffffffffu, s, off);
            if (tid >= off) s += v;
        }
        if (tid < NEXP) off_s[tid + 1] = s;
        if (tid == 0) off_s[0] = 0;
    }
    __syncthreads();
    if (tid <= NEXP) g_off[tid] = off_s[tid];
    if (tid == 0) {
        int nt = 0;
        for (int e = 0; e < NEXP; e++) {
            int cc = cnt[e], base = off_s[e];
            for (int r = 0; r < cc; r += BM) {
                g_tile_expert[nt] = e;
                g_tile_row[nt] = base + r;
                nt++;
            }
        }
        g_num_tiles = nt;
    }
    for (int i = tid; i < NROWS; i += 1024) {
        int e = g_expert_of[i];
        int p = off_s[e] + atomicAdd(&cur[e], 1);
        g_row_token[p] = i >> 3;
        g_pos_of[i] = p;
    }
}

// ============ GEMM1 (launch #4): gate+up, 128M x 96N, single-sync pipeline ============
// smem: A0@0 A1@8192 (swizzled 32B rows; h@0 l@4096 within stage)
//       B0@16384 B1@29696 (gh@0 gl@3328 uh@6656 ul@9984; 208B rows); total 43008
__global__ __launch_bounds__(256) void k_gemm1(const float* __restrict__ Wg,
                                               const float* __restrict__ Wu) {
    int mt = blockIdx.y;
    if (mt >= g_num_tiles) return;
    int e = g_tile_expert[mt], row0 = g_tile_row[mt], row_end = g_off[e + 1];
    int n0 = blockIdx.x * 96;

    __shared__ __align__(128) char smem[43008];
    uint32_t sb = smem_u32(smem);
    int tid = threadIdx.x, wid = tid >> 5, lane = tid & 31;
    int wm0 = (wid >> 1) * 32, nio = wid & 1;

    // A staging: each thread owns (row r, chunk c2) for both h and l
    int r = tid >> 1, c2 = tid & 1;
    int gr = row0 + r; if (gr > NROWS - 1) gr = NROWS - 1;
    int tok = g_row_token[gr];
    const __nv_bfloat16* srcAh = g_Xh + (size_t)tok * DIM + c2 * 8;
    const __nv_bfloat16* srcAl = g_Xl + (size_t)tok * DIM + c2 * 8;
    uint32_t stA = r * 32 + ((c2 ^ ((r >> 2) & 1)) << 4);

    // W staging: 3 float4/thread/chunk  (2 mats x 16k x 24 nq)
    const float* gW[3]; uint32_t stB[3];
#pragma unroll
    for (int i = 0; i < 3; i++) {
        int c = tid + i * 256;
        int mat = c / 384, rem = c - mat * 384;
        int kr = rem / 24, nq = rem - kr * 24;
        const float* W = mat ? Wu : Wg;
        gW[i] = W + ((size_t)e * DIM + kr) * MDIM + n0 + nq * 4;
        stB[i] = mat * 6656 + kr * 208 + nq * 8;
    }

    float accG[2][6][4] = {}, accU[2][6][4] = {};
    uint32_t aOff;
    { int rr = wm0 + (lane & 15), cc = lane >> 4;
      aOff = rr * 32 + ((cc ^ ((rr >> 2) & 1)) << 4); }
    uint32_t bT = ((lane & 7) + ((lane >> 3) & 1) * 8) * 208 + ((lane >> 4) & 1) * 16;

    // prologue: load+store chunk0, load regs for chunk1
    uint4 aRh = *(const uint4*)srcAh, aRl = *(const uint4*)srcAl;
    float4 wR[3];
#pragma unroll
    for (int i = 0; i < 3; i++) wR[i] = *(const float4*)gW[i];
    *(uint4*)(smem + stA) = aRh;
    *(uint4*)(smem + 4096 + stA) = aRl;
#pragma unroll
    for (int i = 0; i < 3; i++) {
        uint2 hh, ll;
        split4pack(wR[i], hh, ll);
        *(uint2*)(smem + 16384 + stB[i]) = hh;
        *(uint2*)(smem + 16384 + stB[i] + 3328) = ll;
    }
    aRh = *(const uint4*)(srcAh + 16); aRl = *(const uint4*)(srcAl + 16);
#pragma unroll
    for (int i = 0; i < 3; i++) wR[i] = *(const float4*)(gW[i] + (size_t)16 * MDIM);

    const int NCH = DIM / 16;  // 128
    for (int kc = 0; kc < NCH; kc++) {
        int st = kc & 1;
        __syncthreads();   // stage st fully written; readers of st^1 retired
        if (kc + 1 < NCH) {
            uint32_t as = (st ^ 1) * 8192;
            *(uint4*)(smem + as + stA) = aRh;
            *(uint4*)(smem + as + 4096 + stA) = aRl;
            uint32_t bs = 16384 + (st ^ 1) * 13312;
#pragma unroll
            for (int i = 0; i < 3; i++) {
                uint2 hh, ll;
                split4pack(wR[i], hh, ll);
                *(uint2*)(smem + bs + stB[i]) = hh;
                *(uint2*)(smem + bs + stB[i] + 3328) = ll;
            }
        }
        if (kc + 2 < NCH) {
            int ko = (kc + 2) * 16;
            aRh = *(const uint4*)(srcAh + ko);
            aRl = *(const uint4*)(srcAl + ko);
#pragma unroll
            for (int i = 0; i < 3; i++)
                wR[i] = *(const float4*)(gW[i] + (size_t)ko * MDIM);
        }
        uint32_t aA = sb + st * 8192 + aOff;
        uint32_t aH0[4], aH1[4], aL0[4], aL1[4];
        LDSM4(aH0, aA); LDSM4(aH1, aA + 512);
        LDSM4(aL0, aA + 4096); LDSM4(aL1, aA + 4608);
        uint32_t bb = sb + 16384 + st * 13312 + bT;
#pragma unroll
        for (int g = 0; g < 3; g++) {
            uint32_t b[4];
            uint32_t uoff = (2 * g + nio) * 32;
            int j0 = 2 * g;
            LDSM4T(b, bb + uoff);            // gate hi
            MMA4(accG, j0, aH0, aH1, b);
            MMA4(accG, j0, aL0, aL1, b);
            LDSM4T(b, bb + 3328 + uoff);     // gate lo (Ah only)
            MMA4(accG, j0, aH0, aH1, b);
            LDSM4T(b, bb + 6656 + uoff);     // up hi
            MMA4(accU, j0, aH0, aH1, b);
            MMA4(accU, j0, aL0, aL1, b);
            LDSM4T(b, bb + 9984 + uoff);     // up lo (Ah only)
            MMA4(accU, j0, aH0, aH1, b);
        }
    }

    // epilogue: silu(g)*u -> split bf16
#pragma unroll
    for (int f = 0; f < 2; f++) {
        int rl = row0 + wm0 + f * 16 + (lane >> 2);
        int rh = rl + 8;
#pragma unroll
        for (int j = 0; j < 6; j++) {
            int c = n0 + (2 * (j >> 1) + nio) * 16 + (j & 1) * 8 + (lane & 3) * 2;
            float g0 = accG[f][j][0], g1 = accG[f][j][1];
            float g2 = accG[f][j][2], g3 = accG[f][j][3];
            float u0 = accU[f][j][0], u1 = accU[f][j][1];
            float u2 = accU[f][j][2], u3 = accU[f][j][3];
            float v0 = (g0 / (1.f + __expf(-g0))) * u0;
            float v1 = (g1 / (1.f + __expf(-g1))) * u1;
            float v2 = (g2 / (1.f + __expf(-g2))) * u2;
            float v3 = (g3 / (1.f + __expf(-g3))) * u3;
            __nv_bfloat16 h0, l0, h1, l1, h2, l2, h3, l3;
            split2(v0, h0, l0); split2(v1, h1, l1);
            split2(v2, h2, l2); split2(v3, h3, l3);
            if (rl < row_end) {
                *(uint32_t*)(g_Ih + (size_t)rl * MDIM + c) = pack2(h0, h1);
                *(uint32_t*)(g_Il + (size_t)rl * MDIM + c) = pack2(l0, l1);
            }
            if (rh < row_end) {
                *(uint32_t*)(g_Ih + (size_t)rh * MDIM + c) = pack2(h2, h3);
                *(uint32_t*)(g_Il + (size_t)rh * MDIM + c) = pack2(l2, l3);
            }
        }
    }
}

// ============ GEMM2 (launch #5): down proj, 128M x 128N, single-sync ============
// smem: A0@0 A1@8192 (swizzled); B0@16384 B1@25088 (dh@0 dl@4352; 272B rows); total 33792
__global__ __launch_bounds__(256) void k_gemm2(const float* __restrict__ Wd) {
    int mt = blockIdx.y;
    if (mt >= g_num_tiles) return;
    int e = g_tile_expert[mt], row0 = g_tile_row[mt], row_end = g_off[e + 1];
    int n0 = blockIdx.x * 128;

    __shared__ __align__(128) char smem[33792];
    uint32_t sb = smem_u32(smem);
    int tid = threadIdx.x, wid = tid >> 5, lane = tid & 31;
    int wm0 = (wid >> 1) * 32, nio = wid & 1;

    int r = tid >> 1, c2 = tid & 1;
    int gr = row0 + r; if (gr > NROWS - 1) gr = NROWS - 1;
    const __nv_bfloat16* srcAh = g_Ih + (size_t)gr * MDIM + c2 * 8;
    const __nv_bfloat16* srcAl = g_Il + (size_t)gr * MDIM + c2 * 8;
    uint32_t stA = r * 32 + ((c2 ^ ((r >> 2) & 1)) << 4);

    const float* gW[2]; uint32_t stB[2];
#pragma unroll
    for (int i = 0; i < 2; i++) {
        int c = tid + i * 256;
        int kr = c >> 5, nq = c & 31;
        gW[i] = Wd + ((size_t)e * MDIM + kr) * DIM + n0 + nq * 4;
        stB[i] = kr * 272 + nq * 8;
    }

    float acc[2][8][4] = {};
    uint32_t aOff;
    { int rr = wm0 + (lane & 15), cc = lane >> 4;
      aOff = rr * 32 + ((cc ^ ((rr >> 2) & 1)) << 4); }
    uint32_t bT = ((lane & 7) + ((lane >> 3) & 1) * 8) * 272 + ((lane >> 4) & 1) * 16;

    uint4 aRh = *(const uint4*)srcAh, aRl = *(const uint4*)srcAl;
    float4 wR[2];
#pragma unroll
    for (int i = 0; i < 2; i++) wR[i] = *(const float4*)gW[i];
    *(uint4*)(smem + stA) = aRh;
    *(uint4*)(smem + 4096 + stA) = aRl;
#pragma unroll
    for (int i = 0; i < 2; i++) {
        uint2 hh, ll;
        split4pack(wR[i], hh, ll);
        *(uint2*)(smem + 16384 + stB[i]) = hh;
        *(uint2*)(smem + 16384 + stB[i] + 4352) = ll;
    }
    aRh = *(const uint4*)(srcAh + 16); aRl = *(const uint4*)(srcAl + 16);
#pragma unroll
    for (int i = 0; i < 2; i++) wR[i] = *(const float4*)(gW[i] + (size_t)16 * DIM);

    const int NCH = MDIM / 16;  // 48
    for (int kc = 0; kc < NCH; kc++) {
        int st = kc & 1;
        __syncthreads();
        if (kc + 1 < NCH) {
            uint32_t as = (st ^ 1) * 8192;
            *(uint4*)(smem + as + stA) = aRh;
            *(uint4*)(smem + as + 4096 + stA) = aRl;
            uint32_t bs = 16384 + (st ^ 1) * 8704;
#pragma unroll
            for (int i = 0; i < 2; i++) {
                uint2 hh, ll;
                split4pack(wR[i], hh, ll);
                *(uint2*)(smem + bs + stB[i]) = hh;
                *(uint2*)(smem + bs + stB[i] + 4352) = ll;
            }
        }
        if (kc + 2 < NCH) {
            int ko = (kc + 2) * 16;
            aRh = *(const uint4*)(srcAh + ko);
            aRl = *(const uint4*)(srcAl + ko);
#pragma unroll
            for (int i = 0; i < 2; i++)
                wR[i] = *(const float4*)(gW[i] + (size_t)ko * DIM);
        }
        uint32_t aA = sb + st * 8192 + aOff;
        uint32_t aH0[4], aH1[4], aL0[4], aL1[4];
        LDSM4(aH0, aA); LDSM4(aH1, aA + 512);
        LDSM4(aL0, aA + 4096); LDSM4(aL1, aA + 4608);
        uint32_t bb = sb + 16384 + st * 8704 + bT;
#pragma unroll
        for (int g = 0; g < 4; g++) {
            uint32_t b[4];
            uint32_t uoff = (2 * g + nio) * 32;
            int j0 = 2 * g;
            LDSM4T(b, bb + uoff);            // down hi
            MMA4(acc, j0, aH0, aH1, b);
            MMA4(acc, j0, aL0, aL1, b);
            LDSM4T(b, bb + 4352 + uoff);     // down lo (Ah only)
            MMA4(acc, j0, aH0, aH1, b);
        }
    }

#pragma unroll
    for (int f = 0; f < 2; f++) {
        int rl = row0 + wm0 + f * 16 + (lane >> 2);
        int rh = rl + 8;
#pragma unroll
        for (int j = 0; j < 8; j++) {
            int c = n0 + (2 * (j >> 1) + nio) * 16 + (j & 1) * 8 + (lane & 3) * 2;
            if (rl < row_end)
                *(float2*)(g_eout + (size_t)rl * DIM + c) = make_float2(acc[f][j][0], acc[f][j][1]);
            if (rh < row_end)
                *(float2*)(g_eout + (size_t)rh * DIM + c) = make_float2(acc[f][j][2], acc[f][j][3]);
        }
    }
}

// ============ combine (launch #6) ============
__global__ __launch_bounds__(256) void k_combine(float* __restrict__ out) {
    int t = blockIdx.x;
    __shared__ float w[TOPK];
    __shared__ int   ps[TOPK];
    if (threadIdx.x < TOPK) {
        w[threadIdx.x]  = g_weight_of[t * TOPK + threadIdx.x];
        ps[threadIdx.x] = g_pos_of[t * TOPK + threadIdx.x];
    }
    __syncthreads();
    for (int d = threadIdx.x; d < DIM; d += 256) {
        float s = 0.f;
#pragma unroll
        for (int k = 0; k < TOPK; k++)
            s += w[k] * g_eout[(size_t)ps[k] * DIM + d];
        out[(size_t)t * DIM + d] = s;
    }
}

// ============ launch ============
extern "C" void kernel_launch(void* const* d_in, const int* in_sizes, int n_in,
                              void* d_out, int out_size) {
    const float* x  = (const float*)d_in[0];
    const float* gk = (const float*)d_in[1];
    const float* wg = (const float*)d_in[2];
    const float* wu = (const float*)d_in[3];
    const float* wd = (const float*)d_in[4];
    float* out = (float*)d_out;

    k_convert_x<<<TOKENS, 256>>>(x);
    k_router<<<TOKENS / 64, 256>>>(x, gk);
    k_prefix_scatter<<<1, 1024>>>();
    k_gemm1<<<dim3(MDIM / 96, MAX_TILES), 256>>>(wg, wu);
    k_gemm2<<<dim3(DIM / 128, MAX_TILES), 256>>>(wd);
    k_combine<<<TOKENS, 256>>>(out);
}

// round 13
// speedup vs baseline: 1.1738x; 1.0011x over previous
#include <cuda_runtime.h>
#include <cuda_bf16.h>
#include <stdint.h>
#include <math.h>

#define TOKENS 4096
#define DIM    2048
#define NEXP   32
#define TOPK   8
#define MDIM   768
#define NROWS  (TOKENS*TOPK)
#define BM     128
#define MAX_TILES 288

__device__ __forceinline__ uint32_t smem_u32(const void* p) {
    uint32_t a;
    asm("{ .reg .u64 t; cvta.to.shared.u64 t, %1; cvt.u32.u64 %0, t; }" : "=r"(a) : "l"(p));
    return a;
}

#define LDSM4(r, addr) \
    asm volatile("ldmatrix.sync.aligned.m8n8.x4.shared.b16 {%0,%1,%2,%3}, [%4];" \
        : "=r"((r)[0]), "=r"((r)[1]), "=r"((r)[2]), "=r"((r)[3]) : "r"(addr))

#define LDSM4T(r, addr) \
    asm volatile("ldmatrix.sync.aligned.m8n8.x4.trans.shared.b16 {%0,%1,%2,%3}, [%4];" \
        : "=r"((r)[0]), "=r"((r)[1]), "=r"((r)[2]), "=r"((r)[3]) : "r"(addr))

#define MMA_BF16(d, a, b0v, b1v) \
    asm volatile("mma.sync.aligned.m16n8k16.row.col.f32.bf16.bf16.f32 " \
        "{%0,%1,%2,%3},{%4,%5,%6,%7},{%8,%9},{%0,%1,%2,%3};" \
        : "+f"((d)[0]), "+f"((d)[1]), "+f"((d)[2]), "+f"((d)[3]) \
        : "r"((a)[0]), "r"((a)[1]), "r"((a)[2]), "r"((a)[3]), "r"(b0v), "r"(b1v))

#define MMA4(acc, j0, A0, A1, b) do { \
    MMA_BF16(acc[0][j0],   A0, (b)[0], (b)[1]); \
    MMA_BF16(acc[0][j0+1], A0, (b)[2], (b)[3]); \
    MMA_BF16(acc[1][j0],   A1, (b)[0], (b)[1]); \
    MMA_BF16(acc[1][j0+1], A1, (b)[2], (b)[3]); \
} while(0)

__device__ __forceinline__ void split2(float v, __nv_bfloat16& h, __nv_bfloat16& l) {
    h = __float2bfloat16(v);
    l = __float2bfloat16(v - __bfloat162float(h));
}
__device__ __forceinline__ uint32_t pack2(__nv_bfloat16 a, __nv_bfloat16 b) {
    __nv_bfloat162 t(a, b);
    return *(uint32_t*)&t;
}
// RN split (for activations)
__device__ __forceinline__ void split4pack(float4 v, uint2& hh, uint2& ll) {
    __nv_bfloat16 h0, h1, h2, h3, l0, l1, l2, l3;
    split2(v.x, h0, l0); split2(v.y, h1, l1);
    split2(v.z, h2, l2); split2(v.w, h3, l3);
    hh = make_uint2(pack2(h0, h1), pack2(h2, h3));
    ll = make_uint2(pack2(l0, l1), pack2(l2, l3));
}
// Truncation split (for weights): hi = top 16 bits (PRMT), lo = RN bf16 of residual
__device__ __forceinline__ void split4pack_trunc(float4 v, uint2& hh, uint2& ll) {
    uint32_t x0 = __float_as_uint(v.x), x1 = __float_as_uint(v.y);
    uint32_t x2 = __float_as_uint(v.z), x3 = __float_as_uint(v.w);
    hh.x = __byte_perm(x0, x1, 0x7632);
    hh.y = __byte_perm(x2, x3, 0x7632);
    float l0 = v.x - __uint_as_float(x0 & 0xffff0000u);
    float l1 = v.y - __uint_as_float(x1 & 0xffff0000u);
    float l2 = v.z - __uint_as_float(x2 & 0xffff0000u);
    float l3 = v.w - __uint_as_float(x3 & 0xffff0000u);
    uint32_t p0, p1;
    asm("cvt.rn.bf16x2.f32 %0, %1, %2;" : "=r"(p0) : "f"(l1), "f"(l0));
    asm("cvt.rn.bf16x2.f32 %0, %1, %2;" : "=r"(p1) : "f"(l3), "f"(l2));
    ll = make_uint2(p0, p1);
}

// ============ device scratch (~402MB, proven budget) ============
__device__ int   g_off[NEXP + 1];
__device__ int   g_expert_of[NROWS];
__device__ float g_weight_of[NROWS];
__device__ int   g_row_token[NROWS];
__device__ int   g_pos_of[NROWS];
__device__ int   g_tile_expert[MAX_TILES];
__device__ int   g_tile_row[MAX_TILES];
__device__ int   g_num_tiles;
__device__ __nv_bfloat16 g_Xh[(size_t)TOKENS * DIM];
__device__ __nv_bfloat16 g_Xl[(size_t)TOKENS * DIM];
__device__ __nv_bfloat16 g_Ih[(size_t)NROWS * MDIM];
__device__ __nv_bfloat16 g_Il[(size_t)NROWS * MDIM];
__device__ float g_eout[(size_t)NROWS * DIM];

// ============ token fp32 -> split bf16 (launch #1) ============
__global__ __launch_bounds__(256) void k_convert_x(const float* __restrict__ x) {
    int t = blockIdx.x;
    const float4* src = (const float4*)(x + (size_t)t * DIM);
#pragma unroll
    for (int i = 0; i < 2; i++) {
        int idx = threadIdx.x + i * 256;
        uint2 hh, ll;
        split4pack(src[idx], hh, ll);
        *(uint2*)(g_Xh + (size_t)t * DIM + idx * 4) = hh;
        *(uint2*)(g_Xl + (size_t)t * DIM + idx * 4) = ll;
    }
}

// ============ router (launch #2) ============
__global__ __launch_bounds__(256) void k_router(const float* __restrict__ x,
                                                const float* __restrict__ gk) {
    __shared__ float xs[64][64];
    __shared__ float gs[64][32];
    __shared__ float lg[64][32];
    int tid = threadIdx.x, t0 = blockIdx.x * 64, e = tid & 31, r8 = tid >> 5;
    float acc[8];
#pragma unroll
    for (int i = 0; i < 8; i++) acc[i] = 0.f;
    for (int d0 = 0; d0 < DIM; d0 += 64) {
#pragma unroll
        for (int i = 0; i < 4; i++) {
            int f = tid + i * 256, row = f >> 4, dv = f & 15;
            *(float4*)&xs[row][dv * 4] =
                *(const float4*)(x + (size_t)(t0 + row) * DIM + d0 + dv * 4);
        }
#pragma unroll
        for (int i = 0; i < 2; i++) {
            int f = tid + i * 256, dd = f >> 3, ev = f & 7;
            *(float4*)&gs[dd][ev * 4] =
                *(const float4*)(gk + (size_t)(d0 + dd) * NEXP + ev * 4);
        }
        __syncthreads();
#pragma unroll 8
        for (int dd = 0; dd < 64; dd++) {
            float g = gs[dd][e];
#pragma unroll
            for (int rr = 0; rr < 8; rr++) acc[rr] += xs[rr * 8 + r8][dd] * g;
        }
        __syncthreads();
    }
#pragma unroll
    for (int rr = 0; rr < 8; rr++) lg[rr * 8 + r8][e] = acc[rr];
    __syncthreads();

    int w = tid >> 5, lane = tid & 31;
    for (int ti = 0; ti < 8; ti++) {
        int tok = w * 8 + ti;
        float logit = lg[tok][lane];
        unsigned selmask = 0;
        float vals[TOPK]; int ids[TOPK];
#pragma unroll
        for (int k = 0; k < TOPK; k++) {
            float v = ((selmask >> lane) & 1u) ? -1e30f : logit;
            float bv = v; int bi = lane;
#pragma unroll
            for (int off = 16; off; off >>= 1) {
                float ov = __shfl_down_sync(0xffffffffu, bv, off);
                int   oi = __shfl_down_sync(0xffffffffu, bi, off);
                if (ov > bv || (ov == bv && oi < bi)) { bv = ov; bi = oi; }
            }
            bv = __shfl_sync(0xffffffffu, bv, 0);
            bi = __shfl_sync(0xffffffffu, bi, 0);
            vals[k] = bv; ids[k] = bi;
            selmask |= 1u << bi;
        }
        if (lane == 0) {
            float mx = vals[0], s = 0.f, wv[TOPK];
#pragma unroll
            for (int k = 0; k < TOPK; k++) { wv[k] = expf(vals[k] - mx); s += wv[k]; }
            float inv = 1.f / s;
            int t = t0 + tok;
#pragma unroll
            for (int k = 0; k < TOPK; k++) {
                g_weight_of[t * TOPK + k] = wv[k] * inv;
                g_expert_of[t * TOPK + k] = ids[k];
            }
        }
    }
}

// ============ fused histogram + prefix + tile map + scatter (launch #3) ============
__global__ __launch_bounds__(1024) void k_prefix_scatter() {
    __shared__ int cnt[NEXP], off_s[NEXP + 1], cur[NEXP];
    int tid = threadIdx.x;
    if (tid < NEXP) { cnt[tid] = 0; cur[tid] = 0; }
    __syncthreads();
    for (int i = tid; i < NROWS; i += 1024)
        atomicAdd(&cnt[g_expert_of[i]], 1);
    __syncthreads();
    if (tid < 32) {
        int c = (tid < NEXP) ? cnt[tid] : 0;
        int s = c;
#pragma unroll
        for (int off = 1; off < 32; off <<= 1) {
            int v = __shfl_up_sync(0xffffffffu, s, off);
            if (tid >= off) s += v;
        }
        if (tid < NEXP) off_s[tid + 1] = s;
        if (tid == 0) off_s[0] = 0;
    }
    __syncthreads();
    if (tid <= NEXP) g_off[tid] = off_s[tid];
    if (tid == 0) {
        int nt = 0;
        for (int e = 0; e < NEXP; e++) {
            int cc = cnt[e], base = off_s[e];
            for (int r = 0; r < cc; r += BM) {
                g_tile_expert[nt] = e;
                g_tile_row[nt] = base + r;
                nt++;
            }
        }
        g_num_tiles = nt;
    }
    for (int i = tid; i < NROWS; i += 1024) {
        int e = g_expert_of[i];
        int p = off_s[e] + atomicAdd(&cur[e], 1);
        g_row_token[p] = i >> 3;
        g_pos_of[i] = p;
    }
}

// ============ GEMM1 (launch #4): gate+up, 128M x 96N, 384 thr (12 warps 4Mx3N) ============
// smem: A0@0 A1@8192 (swizzled 32B rows; h@0 l@4096)
//       B0@16384 B1@29696 (gh@0 gl@3328 uh@6656 ul@9984; 208B rows); total 43008
__global__ __launch_bounds__(384) void k_gemm1(const float* __restrict__ Wg,
                                               const float* __restrict__ Wu) {
    int mt = blockIdx.y;
    if (mt >= g_num_tiles) return;
    int e = g_tile_expert[mt], row0 = g_tile_row[mt], row_end = g_off[e + 1];
    int n0 = blockIdx.x * 96;

    __shared__ __align__(128) char smem[43008];
    uint32_t sb = smem_u32(smem);
    int tid = threadIdx.x, wid = tid >> 5, lane = tid & 31;
    int wm0 = (wid & 3) * 32, wn0w = (wid >> 2) * 32;   // 4 M-warps x 3 N-warps

    // A staging: threads 0..255 own (row, chunk-half); threads 256+ skip A
    bool doA = tid < 256;
    int r = tid >> 1, c2 = tid & 1;
    int gr = row0 + (doA ? r : 0); if (gr > NROWS - 1) gr = NROWS - 1;
    int tok = g_row_token[gr];
    const __nv_bfloat16* srcAh = g_Xh + (size_t)tok * DIM + c2 * 8;
    const __nv_bfloat16* srcAl = g_Xl + (size_t)tok * DIM + c2 * 8;
    uint32_t stA = r * 32 + ((c2 ^ ((r >> 2) & 1)) << 4);

    // W staging: 768 float4 slots, 2/thread
    const float* gW[2]; uint32_t stB[2];
#pragma unroll
    for (int i = 0; i < 2; i++) {
        int c = tid + i * 384;
        int mat = c >= 384 ? 1 : 0, rem = c - mat * 384;
        int kr = rem / 24, nq = rem - kr * 24;
        const float* W = mat ? Wu : Wg;
        gW[i] = W + ((size_t)e * DIM + kr) * MDIM + n0 + nq * 4;
        stB[i] = mat * 6656 + kr * 208 + nq * 8;
    }

    float accG[2][4][4] = {}, accU[2][4][4] = {};
    uint32_t aOff;
    { int rr = wm0 + (lane & 15), cc = lane >> 4;
      aOff = rr * 32 + ((cc ^ ((rr >> 2) & 1)) << 4); }
    uint32_t bT = ((lane & 7) + ((lane >> 3) & 1) * 8) * 208 + ((lane >> 4) & 1) * 16
                + wn0w * 2;

    // prologue: chunk0 store, chunk1 regs
    uint4 aRh, aRl;
    float4 wR[2];
    if (doA) { aRh = *(const uint4*)srcAh; aRl = *(const uint4*)srcAl; }
#pragma unroll
    for (int i = 0; i < 2; i++) wR[i] = *(const float4*)gW[i];
    if (doA) {
        *(uint4*)(smem + stA) = aRh;
        *(uint4*)(smem + 4096 + stA) = aRl;
    }
#pragma unroll
    for (int i = 0; i < 2; i++) {
        uint2 hh, ll;
        split4pack_trunc(wR[i], hh, ll);
        *(uint2*)(smem + 16384 + stB[i]) = hh;
        *(uint2*)(smem + 16384 + stB[i] + 3328) = ll;
    }
    if (doA) { aRh = *(const uint4*)(srcAh + 16); aRl = *(const uint4*)(srcAl + 16); }
#pragma unroll
    for (int i = 0; i < 2; i++) wR[i] = *(const float4*)(gW[i] + (size_t)16 * MDIM);

    const int NCH = DIM / 16;  // 128
    for (int kc = 0; kc < NCH; kc++) {
        int st = kc & 1;
        __syncthreads();
        if (kc + 1 < NCH) {
            if (doA) {
                uint32_t as = (st ^ 1) * 8192;
                *(uint4*)(smem + as + stA) = aRh;
                *(uint4*)(smem + as + 4096 + stA) = aRl;
            }
            uint32_t bs = 16384 + (st ^ 1) * 13312;
#pragma unroll
            for (int i = 0; i < 2; i++) {
                uint2 hh, ll;
                split4pack_trunc(wR[i], hh, ll);
                *(uint2*)(smem + bs + stB[i]) = hh;
                *(uint2*)(smem + bs + stB[i] + 3328) = ll;
            }
        }
        if (kc + 2 < NCH) {
            int ko = (kc + 2) * 16;
            if (doA) {
                aRh = *(const uint4*)(srcAh + ko);
                aRl = *(const uint4*)(srcAl + ko);
            }
#pragma unroll
            for (int i = 0; i < 2; i++)
                wR[i] = *(const float4*)(gW[i] + (size_t)ko * MDIM);
        }
        uint32_t aA = sb + st * 8192 + aOff;
        uint32_t aH0[4], aH1[4], aL0[4], aL1[4];
        LDSM4(aH0, aA); LDSM4(aH1, aA + 512);
        LDSM4(aL0, aA + 4096); LDSM4(aL1, aA + 4608);
        uint32_t bb = sb + 16384 + st * 13312 + bT;
#pragma unroll
        for (int g = 0; g < 2; g++) {
            uint32_t b[4];
            uint32_t uoff = g * 32;
            int j0 = 2 * g;
            LDSM4T(b, bb + uoff);            // gate hi
            MMA4(accG, j0, aH0, aH1, b);
            MMA4(accG, j0, aL0, aL1, b);
            LDSM4T(b, bb + 3328 + uoff);     // gate lo (Ah only)
            MMA4(accG, j0, aH0, aH1, b);
            LDSM4T(b, bb + 6656 + uoff);     // up hi
            MMA4(accU, j0, aH0, aH1, b);
            MMA4(accU, j0, aL0, aL1, b);
            LDSM4T(b, bb + 9984 + uoff);     // up lo (Ah only)
            MMA4(accU, j0, aH0, aH1, b);
        }
    }

    // epilogue: silu(g)*u -> split bf16
#pragma unroll
    for (int f = 0; f < 2; f++) {
        int rl = row0 + wm0 + f * 16 + (lane >> 2);
        int rh = rl + 8;
#pragma unroll
        for (int j = 0; j < 4; j++) {
            int c = n0 + wn0w + j * 8 + (lane & 3) * 2;
            float g0 = accG[f][j][0], g1 = accG[f][j][1];
            float g2 = accG[f][j][2], g3 = accG[f][j][3];
            float u0 = accU[f][j][0], u1 = accU[f][j][1];
            float u2 = accU[f][j][2], u3 = accU[f][j][3];
            float v0 = (g0 / (1.f + __expf(-g0))) * u0;
            float v1 = (g1 / (1.f + __expf(-g1))) * u1;
            float v2 = (g2 / (1.f + __expf(-g2))) * u2;
            float v3 = (g3 / (1.f + __expf(-g3))) * u3;
            __nv_bfloat16 h0, l0, h1, l1, h2, l2, h3, l3;
            split2(v0, h0, l0); split2(v1, h1, l1);
            split2(v2, h2, l2); split2(v3, h3, l3);
            if (rl < row_end) {
                *(uint32_t*)(g_Ih + (size_t)rl * MDIM + c) = pack2(h0, h1);
                *(uint32_t*)(g_Il + (size_t)rl * MDIM + c) = pack2(l0, l1);
            }
            if (rh < row_end) {
                *(uint32_t*)(g_Ih + (size_t)rh * MDIM + c) = pack2(h2, h3);
                *(uint32_t*)(g_Il + (size_t)rh * MDIM + c) = pack2(l2, l3);
            }
        }
    }
}

// ============ GEMM2 (launch #5): down proj, 128M x 128N, single-sync (R12) ============
// smem: A0@0 A1@8192 (swizzled); B0@16384 B1@25088 (dh@0 dl@4352; 272B rows); total 33792
__global__ __launch_bounds__(256) void k_gemm2(const float* __restrict__ Wd) {
    int mt = blockIdx.y;
    if (mt >= g_num_tiles) return;
    int e = g_tile_expert[mt], row0 = g_tile_row[mt], row_end = g_off[e + 1];
    int n0 = blockIdx.x * 128;

    __shared__ __align__(128) char smem[33792];
    uint32_t sb = smem_u32(smem);
    int tid = threadIdx.x, wid = tid >> 5, lane = tid & 31;
    int wm0 = (wid >> 1) * 32, nio = wid & 1;

    int r = tid >> 1, c2 = tid & 1;
    int gr = row0 + r; if (gr > NROWS - 1) gr = NROWS - 1;
    const __nv_bfloat16* srcAh = g_Ih + (size_t)gr * MDIM + c2 * 8;
    const __nv_bfloat16* srcAl = g_Il + (size_t)gr * MDIM + c2 * 8;
    uint32_t stA = r * 32 + ((c2 ^ ((r >> 2) & 1)) << 4);

    const float* gW[2]; uint32_t stB[2];
#pragma unroll
    for (int i = 0; i < 2; i++) {
        int c = tid + i * 256;
        int kr = c >> 5, nq = c & 31;
        gW[i] = Wd + ((size_t)e * MDIM + kr) * DIM + n0 + nq * 4;
        stB[i] = kr * 272 + nq * 8;
    }

    float acc[2][8][4] = {};
    uint32_t aOff;
    { int rr = wm0 + (lane & 15), cc = lane >> 4;
      aOff = rr * 32 + ((cc ^ ((rr >> 2) & 1)) << 4); }
    uint32_t bT = ((lane & 7) + ((lane >> 3) & 1) * 8) * 272 + ((lane >> 4) & 1) * 16;

    uint4 aRh = *(const uint4*)srcAh, aRl = *(const uint4*)srcAl;
    float4 wR[2];
#pragma unroll
    for (int i = 0; i < 2; i++) wR[i] = *(const float4*)gW[i];
    *(uint4*)(smem + stA) = aRh;
    *(uint4*)(smem + 4096 + stA) = aRl;
#pragma unroll
    for (int i = 0; i < 2; i++) {
        uint2 hh, ll;
        split4pack_trunc(wR[i], hh, ll);
        *(uint2*)(smem + 16384 + stB[i]) = hh;
        *(uint2*)(smem + 16384 + stB[i] + 4352) = ll;
    }
    aRh = *(const uint4*)(srcAh + 16); aRl = *(const uint4*)(srcAl + 16);
#pragma unroll
    for (int i = 0; i < 2; i++) wR[i] = *(const float4*)(gW[i] + (size_t)16 * DIM);

    const int NCH = MDIM / 16;  // 48
    for (int kc = 0; kc < NCH; kc++) {
        int st = kc & 1;
        __syncthreads();
        if (kc + 1 < NCH) {
            uint32_t as = (st ^ 1) * 8192;
            *(uint4*)(smem + as + stA) = aRh;
            *(uint4*)(smem + as + 4096 + stA) = aRl;
            uint32_t bs = 16384 + (st ^ 1) * 8704;
#pragma unroll
            for (int i = 0; i < 2; i++) {
                uint2 hh, ll;
                split4pack_trunc(wR[i], hh, ll);
                *(uint2*)(smem + bs + stB[i]) = hh;
                *(uint2*)(smem + bs + stB[i] + 4352) = ll;
            }
        }
        if (kc + 2 < NCH) {
            int ko = (kc + 2) * 16;
            aRh = *(const uint4*)(srcAh + ko);
            aRl = *(const uint4*)(srcAl + ko);
#pragma unroll
            for (int i = 0; i < 2; i++)
                wR[i] = *(const float4*)(gW[i] + (size_t)ko * DIM);
        }
        uint32_t aA = sb + st * 8192 + aOff;
        uint32_t aH0[4], aH1[4], aL0[4], aL1[4];
        LDSM4(aH0, aA); LDSM4(aH1, aA + 512);
        LDSM4(aL0, aA + 4096); LDSM4(aL1, aA + 4608);
        uint32_t bb = sb + 16384 + st * 8704 + bT;
#pragma unroll
        for (int g = 0; g < 4; g++) {
            uint32_t b[4];
            uint32_t uoff = (2 * g + nio) * 32;
            int j0 = 2 * g;
            LDSM4T(b, bb + uoff);            // down hi
            MMA4(acc, j0, aH0, aH1, b);
            MMA4(acc, j0, aL0, aL1, b);
            LDSM4T(b, bb + 4352 + uoff);     // down lo (Ah only)
            MMA4(acc, j0, aH0, aH1, b);
        }
    }

#pragma unroll
    for (int f = 0; f < 2; f++) {
        int rl = row0 + wm0 + f * 16 + (lane >> 2);
        int rh = rl + 8;
#pragma unroll
        for (int j = 0; j < 8; j++) {
            int c = n0 + (2 * (j >> 1) + nio) * 16 + (j & 1) * 8 + (lane & 3) * 2;
            if (rl < row_end)
                *(float2*)(g_eout + (size_t)rl * DIM + c) = make_float2(acc[f][j][0], acc[f][j][1]);
            if (rh < row_end)
                *(float2*)(g_eout + (size_t)rh * DIM + c) = make_float2(acc[f][j][2], acc[f][j][3]);
        }
    }
}

// ============ combine (launch #6) ============
__global__ __launch_bounds__(256) void k_combine(float* __restrict__ out) {
    int t = blockIdx.x;
    __shared__ float w[TOPK];
    __shared__ int   ps[TOPK];
    if (threadIdx.x < TOPK) {
        w[threadIdx.x]  = g_weight_of[t * TOPK + threadIdx.x];
        ps[threadIdx.x] = g_pos_of[t * TOPK + threadIdx.x];
    }
    __syncthreads();
    for (int d = threadIdx.x; d < DIM; d += 256) {
        float s = 0.f;
#pragma unroll
        for (int k = 0; k < TOPK; k++)
            s += w[k] * g_eout[(size_t)ps[k] * DIM + d];
        out[(size_t)t * DIM + d] = s;
    }
}

// ============ launch ============
extern "C" void kernel_launch(void* const* d_in, const int* in_sizes, int n_in,
                              void* d_out, int out_size) {
    const float* x  = (const float*)d_in[0];
    const float* gk = (const float*)d_in[1];
    const float* wg = (const float*)d_in[2];
    const float* wu = (const float*)d_in[3];
    const float* wd = (const float*)d_in[4];
    float* out = (float*)d_out;

    k_convert_x<<<TOKENS, 256>>>(x);
    k_router<<<TOKENS / 64, 256>>>(x, gk);
    k_prefix_scatter<<<1, 1024>>>();
    k_gemm1<<<dim3(MDIM / 96, MAX_TILES), 384>>>(wg, wu);
    k_gemm2<<<dim3(DIM / 128, MAX_TILES), 256>>>(wd);
    k_combine<<<TOKENS, 256>>>(out);
}